// round 9
// baseline (speedup 1.0000x reference)
#include <cuda_runtime.h>
#include <cuda_bf16.h>
#include <math_constants.h>
#include <cfloat>

#define BATCH 8
#define NPTS 2500
#define NUM_PATCHES 25
#define PATCH_P 100
#define TOTAL_PTS (BATCH * NPTS)             // 20000
#define TOTAL_PATCHES (BATCH * NUM_PATCHES)  // 200

#define WPB 16                 // warps (=queries) per block
#define NSTEP_G 79             // ceil(2500/32)
#define NPAD_G (NSTEP_G * 32)  // 2528
#define NSTEP_P 4              // patch padded to 128

#define GBLK_PER_B 157                      // ceil(2500/16)
#define GBLKS (GBLK_PER_B * BATCH)          // 1256
#define PBLKS (TOTAL_PTS / WPB)             // 1250
#define FUSED_BLKS (GBLKS + PBLKS)          // 2506

#define PAD_COORD 1.0e18f      // padded points: d^2 ~ 3e36, never selected
#define BUFCAP 256             // per-warp candidate-index buffer (ushort)

__device__ float g_cov_global[TOTAL_PTS * 6];
__device__ float g_cov_patch[TOTAL_PTS * 6];

// ---------------------------------------------------------------------------
// 3x3 symmetric smallest-eigenvector (double), writes |v|.
// ---------------------------------------------------------------------------
__device__ __forceinline__ void smallest_evec_abs(
    const float* s, float out[3])
{
    double a00 = s[0], a01 = s[1], a02 = s[2];
    double a11 = s[3], a12 = s[4], a22 = s[5];

    double p1 = a01 * a01 + a02 * a02 + a12 * a12;
    double q  = (a00 + a11 + a22) * (1.0 / 3.0);
    double d0 = a00 - q, d1 = a11 - q, d2 = a22 - q;
    double p2 = d0 * d0 + d1 * d1 + d2 * d2 + 2.0 * p1;

    double lam;
    if (p2 <= 1e-300) {
        lam = q;
    } else {
        double p   = sqrt(p2 * (1.0 / 6.0));
        double inv = 1.0 / p;
        double b00 = d0 * inv, b11 = d1 * inv, b22 = d2 * inv;
        double b01 = a01 * inv, b02 = a02 * inv, b12 = a12 * inv;
        double detB = b00 * (b11 * b22 - b12 * b12)
                    - b01 * (b01 * b22 - b12 * b02)
                    + b02 * (b01 * b12 - b11 * b02);
        double r = 0.5 * detB;
        r = fmin(1.0, fmax(-1.0, r));
        double phi = acos(r) * (1.0 / 3.0);
        lam = q + 2.0 * p * cos(phi + 2.0943951023931953);
    }

    double r0x = a00 - lam, r0y = a01,       r0z = a02;
    double r1x = a01,       r1y = a11 - lam, r1z = a12;
    double r2x = a02,       r2y = a12,       r2z = a22 - lam;

    double c0x = r0y * r1z - r0z * r1y;
    double c0y = r0z * r1x - r0x * r1z;
    double c0z = r0x * r1y - r0y * r1x;

    double c1x = r0y * r2z - r0z * r2y;
    double c1y = r0z * r2x - r0x * r2z;
    double c1z = r0x * r2y - r0y * r2x;

    double c2x = r1y * r2z - r1z * r2y;
    double c2y = r1z * r2x - r1x * r2z;
    double c2z = r1x * r2y - r1y * r2x;

    double n0 = c0x * c0x + c0y * c0y + c0z * c0z;
    double n1 = c1x * c1x + c1y * c1y + c1z * c1z;
    double n2 = c2x * c2x + c2y * c2y + c2z * c2z;

    double vx = c0x, vy = c0y, vz = c0z, nn = n0;
    if (n1 > nn) { vx = c1x; vy = c1y; vz = c1z; nn = n1; }
    if (n2 > nn) { vx = c2x; vy = c2y; vz = c2z; nn = n2; }
    if (nn < 1e-300) { vx = 1.0; vy = 0.0; vz = 0.0; nn = 1.0; }

    double invn = rsqrt(nn);
    out[0] = (float)fabs(vx * invn);
    out[1] = (float)fabs(vy * invn);
    out[2] = (float)fabs(vz * invn);
}

// ascending bitonic sort of 32 floats across lanes
__device__ __forceinline__ float sort32f(float k, int lane)
{
    const unsigned FULL = 0xFFFFFFFFu;
#pragma unroll
    for (int size = 2; size <= 32; size <<= 1) {
#pragma unroll
        for (int stride = size >> 1; stride > 0; stride >>= 1) {
            float o = __shfl_xor_sync(FULL, k, stride);
            bool mn = ((lane & size) == 0) == ((lane & stride) == 0);
            k = mn ? fminf(k, o) : fmaxf(k, o);
        }
    }
    return k;
}

__device__ __forceinline__ float qdist2(float4 p, float qx, float qy, float qz)
{
    float dx = p.x - qx, dy = p.y - qy, dz = p.z - qz;
    return fmaf(dx, dx, fmaf(dy, dy, dz * dz));
}

// ---------------------------------------------------------------------------
// Exact warp kNN: float-only selection of the K smallest exact d^2, with an
// append buffer of candidate indices (every candidate that ever beats the
// running tau — a superset of the true top-K). Then an exact gather pass
// over the buffer accumulates the covariance of points with d^2 <= tau.
// ---------------------------------------------------------------------------
template <int K>
__device__ __forceinline__ void warp_knn_cov(
    const float4* __restrict__ sp, int nstep,
    unsigned short* __restrict__ buf,   // per-warp, BUFCAP entries
    float qx, float qy, float qz, int lane, float* __restrict__ cb)
{
    const unsigned FULL = 0xFFFFFFFFu;

    // ---- step 0: all 32 candidates enter; straight sort seeds the array
    float k0 = qdist2(sp[lane], qx, qy, qz);
    buf[lane] = (unsigned short)lane;
    int cnt = 32;
    float v = sort32f(k0, lane);
    float tau = __shfl_sync(FULL, v, K - 1);

    // ---- selection scan
    for (int n = 1; n < nstep; ++n) {
        const int j = n * 32 + lane;
        float key = qdist2(sp[j], qx, qy, qz);

        unsigned mask = __ballot_sync(FULL, key < tau);
        if (mask) {
            // append the hit candidates' indices (ballot-prefix offsets)
            if (key < tau) {
                int off = cnt + __popc(mask & ((1u << lane) - 1u));
                if (off < BUFCAP) buf[off] = (unsigned short)j;
            }
            cnt += __popc(mask);

            if (__popc(mask) <= 8) {
                // serial sorted insertions
                do {
                    int src = __ffs(mask) - 1;
                    mask &= mask - 1;
                    float k  = __shfl_sync(FULL, key, src);
                    float vp = __shfl_up_sync(FULL, v, 1);
                    if (lane == 0) vp = -CUDART_INF_F;
                    v = (v < k) ? v : ((vp < k) ? k : vp);
                } while (mask);
            } else {
                float s = sort32f(key, lane);
                float r = __shfl_sync(FULL, s, 31 - lane);
                v = fminf(v, r);
#pragma unroll
                for (int stride = 16; stride > 0; stride >>= 1) {
                    float o = __shfl_xor_sync(FULL, v, stride);
                    v = ((lane & stride) == 0) ? fminf(v, o) : fmaxf(v, o);
                }
            }
            tau = __shfl_sync(FULL, v, K - 1);
        }
    }

    if (cnt > BUFCAP) cnt = BUFCAP;

    // ---- exact gather over the buffered candidates
    float xx = 0.f, xy = 0.f, xz = 0.f, yy = 0.f, yz = 0.f, zz = 0.f;
    const int steps = (cnt + 31) >> 5;
    for (int s = 0; s < steps; ++s) {
        const int t = s * 32 + lane;
        if (t < cnt) {
            float4 p = sp[buf[t]];
            float d2 = qdist2(p, qx, qy, qz);
            if (d2 <= tau) {
                float dx = p.x - qx, dy = p.y - qy, dz = p.z - qz;
                xx = fmaf(dx, dx, xx);
                xy = fmaf(dx, dy, xy);
                xz = fmaf(dx, dz, xz);
                yy = fmaf(dy, dy, yy);
                yz = fmaf(dy, dz, yz);
                zz = fmaf(dz, dz, zz);
            }
        }
    }

#pragma unroll
    for (int off = 16; off > 0; off >>= 1) {
        xx += __shfl_xor_sync(FULL, xx, off);
        xy += __shfl_xor_sync(FULL, xy, off);
        xz += __shfl_xor_sync(FULL, xz, off);
        yy += __shfl_xor_sync(FULL, yy, off);
        yz += __shfl_xor_sync(FULL, yz, off);
        zz += __shfl_xor_sync(FULL, zz, off);
    }
    if (lane == 0) {
        cb[0] = xx; cb[1] = xy; cb[2] = xz;
        cb[3] = yy; cb[4] = yz; cb[5] = zz;
    }
}

// ---------------------------------------------------------------------------
// Fused kNN kernel. Blocks [0, GBLKS): global 32-NN. Rest: patch 16-NN.
// Block 0 also zeroes the output accumulator (stream order precedes loss).
// ---------------------------------------------------------------------------
__global__ void __launch_bounds__(512, 4)
knn_fused_kernel(const float* __restrict__ pc, float* __restrict__ out)
{
    __shared__ float4 sp[NPAD_G];                       // 40448 B
    __shared__ unsigned short abuf[WPB * BUFCAP];       //  8192 B

    const int warp = threadIdx.x >> 5;
    const int lane = threadIdx.x & 31;
    unsigned short* buf = abuf + warp * BUFCAP;

    if (blockIdx.x == 0 && threadIdx.x == 0) out[0] = 0.0f;

    if (blockIdx.x < GBLKS) {
        // -------- global 32-NN --------
        const int b  = blockIdx.x / GBLK_PER_B;
        const int qb = blockIdx.x % GBLK_PER_B;
        const float* base = pc + (size_t)b * NPTS * 3;

        for (int j = threadIdx.x; j < NPAD_G; j += 512) {
            float4 val = make_float4(PAD_COORD, PAD_COORD, PAD_COORD, 0.f);
            if (j < NPTS) {
                val = make_float4(base[3 * j + 0], base[3 * j + 1],
                                  base[3 * j + 2], 0.f);
            }
            sp[j] = val;
        }
        __syncthreads();

        const int q = qb * WPB + warp;
        if (q >= NPTS) return;

        const float4 qv = sp[q];
        warp_knn_cov<32>(sp, NSTEP_G, buf, qv.x, qv.y, qv.z, lane,
                         g_cov_global + (size_t)(b * NPTS + q) * 6);
    } else {
        // -------- patch 16-NN: 16 queries spanning <= 2 patches --------
        const int pblk = blockIdx.x - GBLKS;
        const int q0 = pblk * WPB;
        const int p0 = q0 / PATCH_P;

        for (int t = threadIdx.x; t < 256; t += 512) {
            const int which = t >> 7;
            const int local = t & 127;
            const int pp = p0 + which;
            float4 val = make_float4(PAD_COORD, PAD_COORD, PAD_COORD, 0.f);
            if (local < PATCH_P && pp < TOTAL_PATCHES) {
                const float* bb = pc + (size_t)pp * PATCH_P * 3;
                val = make_float4(bb[3 * local + 0], bb[3 * local + 1],
                                  bb[3 * local + 2], 0.f);
            }
            sp[(which << 7) + local] = val;
        }
        __syncthreads();

        const int gq = q0 + warp;
        const int pp = gq / PATCH_P;
        const int ql = gq % PATCH_P;
        const float4* spl = sp + ((pp - p0) << 7);

        const float4 qv = spl[ql];
        warp_knn_cov<16>(spl, NSTEP_P, buf, qv.x, qv.y, qv.z, lane,
                         g_cov_patch + (size_t)gq * 6);
    }
}

// ---------------------------------------------------------------------------
// Loss: one eigen per thread (even threads: global, odd: patch), combine via
// shfl with the adjacent lane, mean-reduce.
// ---------------------------------------------------------------------------
__global__ void __launch_bounds__(128)
loss_kernel(float* __restrict__ out)
{
    const int t = blockIdx.x * 128 + threadIdx.x;
    const int i = t >> 1;               // point id
    const int which = t & 1;            // 0 = global, 1 = patch

    float v = 0.0f;
    if (i < TOTAL_PTS) {
        const float* cb = which ? (g_cov_patch  + (size_t)i * 6)
                                : (g_cov_global + (size_t)i * 6);
        float nv[3];
        smallest_evec_abs(cb, nv);
        float ox = __shfl_xor_sync(0xFFFFFFFFu, nv[0], 1);
        float oy = __shfl_xor_sync(0xFFFFFFFFu, nv[1], 1);
        float oz = __shfl_xor_sync(0xFFFFFFFFu, nv[2], 1);
        if (which == 0) {
            float dx = ox - nv[0], dy = oy - nv[1], dz = oz - nv[2];
            v = sqrtf(fmaf(dx, dx, fmaf(dy, dy, dz * dz)));
        }
    }
#pragma unroll
    for (int off = 16; off > 0; off >>= 1)
        v += __shfl_down_sync(0xFFFFFFFFu, v, off);

    __shared__ float warpsum[4];
    const int lane = threadIdx.x & 31;
    const int wid  = threadIdx.x >> 5;
    if (lane == 0) warpsum[wid] = v;
    __syncthreads();

    if (wid == 0) {
        float s = (lane < 4) ? warpsum[lane] : 0.0f;
#pragma unroll
        for (int off = 2; off > 0; off >>= 1)
            s += __shfl_down_sync(0xFFFFFFFFu, s, off);
        if (lane == 0)
            atomicAdd(out, s * (1.0f / (float)TOTAL_PTS));
    }
}

// ---------------------------------------------------------------------------
extern "C" void kernel_launch(void* const* d_in, const int* in_sizes, int n_in,
                              void* d_out, int out_size)
{
    const float* pc = (const float*)d_in[0];
    float* out = (float*)d_out;

    knn_fused_kernel<<<FUSED_BLKS, 512>>>(pc, out);
    loss_kernel<<<(2 * TOTAL_PTS + 127) / 128, 128>>>(out);
}